// round 10
// baseline (speedup 1.0000x reference)
#include <cuda_runtime.h>

#define TS    100
#define BB    256
#define DOBS  64
#define DFEAT 512
#define DLAT  512
#define DOUTD 64
#define NB    128   // persistent blocks (<= 148 SMs, all resident)

// d_out layout (element offsets): outs, hs, thetas, ys, delta_outs
#define OUTS_OFF 0
#define HS_OFF   (TS*BB*DOUTD)
#define TH_OFF   (HS_OFF + TS*BB*DLAT)
#define YS_OFF   (TH_OFF + TS*BB*DLAT)
#define DO_OFF   (YS_OFF + TS*BB*DLAT)

typedef unsigned long long ull;

// packed f32x2 helpers (each lane is an independent IEEE fp32 RN op)
__device__ __forceinline__ ull fma2(ull a, ull b, ull c) {
    ull d; asm("fma.rn.f32x2 %0, %1, %2, %3;" : "=l"(d) : "l"(a), "l"(b), "l"(c)); return d;
}
__device__ __forceinline__ ull add2(ull a, ull b) {
    ull d; asm("add.rn.f32x2 %0, %1, %2;" : "=l"(d) : "l"(a), "l"(b)); return d;
}
__device__ __forceinline__ float2 unpack2(ull v) {
    float2 f; asm("mov.b64 {%0, %1}, %2;" : "=f"(f.x), "=f"(f.y) : "l"(v)); return f;
}

// persistent state across steps
__device__ float g_x[BB * DFEAT];    // x(t)
__device__ float g_xin[BB * DOBS];   // x_in(t)

// grid barrier state (self-consistent across graph replays)
__device__ unsigned g_bar_cnt = 0;
__device__ volatile unsigned g_bar_gen = 0;

// shared memory: phase tiles / out+prep staging (union, 34.8 KB max)
union SmemU {
    struct {
        float As[2][32][72];    // duplicated A: [k][2*row+{0,1}]
        float B1s[2][32][32];
        float B2s[2][32][32];
    } ph;
    struct {
        float ysm[2][512];
        float red[2][64];
        float outm[2][64];
        float xinm[2][64];
        float wbuf[4096];       // 16 KB weight stage (W_out 64x64 / W_pre 8x512)
    } op;
};

__device__ __forceinline__ void grid_sync(int tid) {
    __syncthreads();
    if (tid == 0) {
        unsigned gen = g_bar_gen;        // read generation BEFORE arriving
        __threadfence();                 // release my block's writes
        if (atomicAdd(&g_bar_cnt, 1u) == NB - 1) {
            g_bar_cnt = 0;
            __threadfence();
            g_bar_gen = gen + 1;         // release
        } else {
            while (g_bar_gen == gen) __nanosleep(32);
            __threadfence();             // acquire
        }
    }
    __syncthreads();
}

// ---------------------------------------------------------------------------
// Dual-GEMM phase. Mainloop FMA order + per-32k stage-partial folds
// BIT-IDENTICAL to the passing R4..R9 kernels. fp64 epilogue (R4-exact).
// blk -> tile: n0 = (blk&15)*32, m0 = (blk>>4)*32.
// ---------------------------------------------------------------------------
template <int PHASE>
__device__ void do_phase(SmemU& sm, int blk, bool zero_h,
                         const float* __restrict__ W1, const float* __restrict__ b1,
                         const float* __restrict__ W2, const float* __restrict__ b2,
                         const float* __restrict__ noise_t,
                         const float* __restrict__ h_src,
                         float* __restrict__ out1, float* __restrict__ out_th)
{
    const int tid = threadIdx.x;
    const int m0 = (blk >> 4) * 32;
    const int n0 = (blk & 15) * 32;
    const int r0 = (tid >> 4) * 2;
    const int c0 = (tid & 15) * 2;
    const int nstage = zero_h ? 16 : 32;

    const int arow = tid >> 3, aq = tid & 7;

    ull acc1[2] = {0ull, 0ull};
    ull acc2[2] = {0ull, 0ull};

    auto ldA = [&](int s) -> float4 {
        const int k0 = s * 32;
        const float* src; int kb;
        if (k0 < 512) { src = g_x;   kb = k0; }
        else          { src = h_src; kb = k0 - 512; }
        return *(const float4*)&src[(size_t)(m0 + arow) * 512 + kb + aq * 4];
    };
    auto ldB = [&](const float* W, int s) -> float4 {
        return *(const float4*)&W[(size_t)(s * 32 + arow) * 512 + n0 + aq * 4];
    };
    auto stA = [&](float4 v, int buf) {
        *(float2*)&sm.ph.As[buf][aq * 4 + 0][2 * arow] = make_float2(v.x, v.x);
        *(float2*)&sm.ph.As[buf][aq * 4 + 1][2 * arow] = make_float2(v.y, v.y);
        *(float2*)&sm.ph.As[buf][aq * 4 + 2][2 * arow] = make_float2(v.z, v.z);
        *(float2*)&sm.ph.As[buf][aq * 4 + 3][2 * arow] = make_float2(v.w, v.w);
    };
    auto stB = [&](float4 w1v, float4 w2v, int buf) {
        *(float4*)&sm.ph.B1s[buf][arow][aq * 4] = w1v;
        *(float4*)&sm.ph.B2s[buf][arow][aq * 4] = w2v;
    };
    auto compute = [&](int buf) {
        ull p1[2] = {0ull, 0ull};
        ull p2[2] = {0ull, 0ull};
#pragma unroll
        for (int kk = 0; kk < 32; kk++) {
            ulonglong2 a01 = *(const ulonglong2*)&sm.ph.As[buf][kk][2 * r0];
            ull w1p = *(const ull*)&sm.ph.B1s[buf][kk][c0];
            ull w2p = *(const ull*)&sm.ph.B2s[buf][kk][c0];
            p1[0] = fma2(a01.x, w1p, p1[0]);
            p2[0] = fma2(a01.x, w2p, p2[0]);
            p1[1] = fma2(a01.y, w1p, p1[1]);
            p2[1] = fma2(a01.y, w2p, p2[1]);
        }
        acc1[0] = add2(acc1[0], p1[0]);
        acc1[1] = add2(acc1[1], p1[1]);
        acc2[0] = add2(acc2[0], p2[0]);
        acc2[1] = add2(acc2[1], p2[1]);
    };

    { // stage 0
        float4 a0 = ldA(0), w10 = ldB(W1, 0), w20 = ldB(W2, 0);
        stA(a0, 0);
        stB(w10, w20, 0);
    }
    __syncthreads();

    for (int s = 0; s < nstage; s++) {
        const int buf = s & 1;
        float4 aN, w1N, w2N;
        const bool more = (s + 1 < nstage);
        if (more) { aN = ldA(s + 1); w1N = ldB(W1, s + 1); w2N = ldB(W2, s + 1); }
        compute(buf);
        if (more) { stA(aN, buf ^ 1); stB(w1N, w2N, buf ^ 1); }
        __syncthreads();
    }

#pragma unroll
    for (int i = 0; i < 2; i++) {
        const int b = m0 + r0 + i;
        float2 v1 = unpack2(acc1[i]);
        float2 v2 = unpack2(acc2[i]);
        float a1v[2] = {v1.x, v1.y};
        float a2v[2] = {v2.x, v2.y};
#pragma unroll
        for (int c = 0; c < 2; c++) {
            const int n = n0 + c0 + c;
            if (PHASE == 0) {
                double z = (double)a1v[c] + (double)b1[n]
                         + (double)noise_t[b * DLAT + n];
                float th = (z > 0.0) ? 1.f : 0.f;
                double g  = (z > 0.0) ? tanh(z) : 0.0;
                double hp = zero_h ? 0.0 : (double)h_src[b * DLAT + n];
                double rl = (double)a2v[c] + (double)b2[n];
                float h = (float)(g * tanh(rl) + (1.0 - g) * hp);
                out1[b * DLAT + n]   = h;
                out_th[b * DLAT + n] = th;
            } else {
                double p = (double)a1v[c] + (double)b1[n];
                double o = (double)a2v[c] + (double)b2[n];
                float y = (float)(tanh(p) / (1.0 + exp(-o)));
                out1[b * DLAT + n] = y;
            }
        }
    }
}

// ---------------------------------------------------------------------------
// Persistent megakernel: 100-step scan with grid barriers between phases.
// ---------------------------------------------------------------------------
__global__ __launch_bounds__(256, 1) void mega_kernel(
    const float* __restrict__ obs,   const float* __restrict__ smask,
    const float* __restrict__ noise,
    const float* __restrict__ W_pre, const float* __restrict__ b_pre,
    const float* __restrict__ Wg,    const float* __restrict__ bg,
    const float* __restrict__ Wr,    const float* __restrict__ br,
    const float* __restrict__ Wp,    const float* __restrict__ bp,
    const float* __restrict__ Wo,    const float* __restrict__ bo,
    const float* __restrict__ W_out, const float* __restrict__ b_out,
    float* __restrict__ outs, float* __restrict__ hs, float* __restrict__ ths,
    float* __restrict__ ys,   float* __restrict__ dos_)
{
    __shared__ SmemU sm;
    const int tid = threadIdx.x;
    const int blk = blockIdx.x;
    const int b0  = blk * 2;

    // ---- out (+ next-step prep) using smem-staged weights ----
    auto do_out_prep = [&](int t, bool do_out, bool do_prep, bool first) {
        auto& op = sm.op;
        if (do_out) {
            const float* y_t = ys + (size_t)t * BB * DLAT;
            {
                int r = tid >> 7, q = tid & 127;
                *(float4*)&op.ysm[r][q * 4] =
                    *(const float4*)&y_t[(size_t)(b0 + r) * 512 + q * 4];
            }
            const int o = tid & 63;
            const int rh = tid >> 6;
            const int r = rh & 1;
            const int half = rh >> 1;
            float acc = 0.f;
            for (int s = 0; s < 8; s++) {           // stage = 64 K-rows of W_out
                __syncthreads();
#pragma unroll
                for (int i = 0; i < 4; i++) {       // 1024 float4 slots
                    int slot = tid + i * 256;
                    int kr = slot >> 4, q = slot & 15;
                    *(float4*)&op.wbuf[kr * 64 + q * 4] =
                        *(const float4*)&W_out[(size_t)(s * 64 + kr) * 64 + q * 4];
                }
                __syncthreads();
                float pa = 0.f;
#pragma unroll
                for (int j = 0; j < 32; j++) {
                    int kk = half * 32 + j;
                    pa += op.ysm[r][s * 64 + kk] * op.wbuf[kk * 64 + o];
                }
                acc += pa;
            }
            if (half == 1) op.red[r][o] = acc;
            __syncthreads();
            if (half == 0) {
                float tot = acc + op.red[r][o] + b_out[o];
                const int b = b0 + r;
                float outv = g_xin[b * 64 + o] + tot;
                outs[(size_t)t * BB * 64 + b * 64 + o] = outv;
                dos_[(size_t)t * BB * 64 + b * 64 + o] = tot;
                op.outm[r][o] = outv;
            }
            __syncthreads();
        }
        if (do_prep) {
            const int tp = first ? 0 : t + 1;
            if (tid < 128) {
                const int r = tid >> 6, o = tid & 63;
                const int b = b0 + r;
                float m = first ? 1.f
                                : ((smask[(size_t)tp * BB + b] < 0.5f) ? 1.f : 0.f);
                float xin = (m != 0.f) ? obs[(size_t)tp * BB * 64 + b * 64 + o]
                                       : op.outm[r][o];
                g_xin[b * 64 + o] = xin;
                op.xinm[r][o] = xin;
            }
            __syncthreads();
            const int r2 = tid >> 7;
            const int f0 = (tid & 127) * 4;
            float accM[4] = {0.f, 0.f, 0.f, 0.f};
            for (int s = 0; s < 8; s++) {           // stage = 8 o2-rows of W_pre
                __syncthreads();
#pragma unroll
                for (int i = 0; i < 4; i++) {       // 1024 float4 slots
                    int slot = tid + i * 256;
                    int orow = slot >> 7, q = slot & 127;
                    *(float4*)&op.wbuf[orow * 512 + q * 4] =
                        *(const float4*)&W_pre[(size_t)(s * 8 + orow) * 512 + q * 4];
                }
                __syncthreads();
                float accP[4] = {0.f, 0.f, 0.f, 0.f};
#pragma unroll
                for (int j = 0; j < 8; j++) {
                    float xv = op.xinm[r2][s * 8 + j];
                    float4 w = *(const float4*)&op.wbuf[j * 512 + f0];
                    accP[0] += xv * w.x;
                    accP[1] += xv * w.y;
                    accP[2] += xv * w.z;
                    accP[3] += xv * w.w;
                }
                accM[0] += accP[0]; accM[1] += accP[1];
                accM[2] += accP[2]; accM[3] += accP[3];
            }
#pragma unroll
            for (int j = 0; j < 4; j++)
                g_x[(size_t)(b0 + r2) * 512 + f0 + j] =
                    (float)tanh((double)accM[j] + (double)b_pre[f0 + j]);
        }
    };

    // ---- t = 0 prep (mask forced to 1) ----
    do_out_prep(0, false, true, true);
    grid_sync(tid);

    for (int t = 0; t < TS; t++) {
        const float* hprev = hs + (size_t)(t - 1) * BB * DLAT;  // unused at t==0
        float* ht  = hs  + (size_t)t * BB * DLAT;
        float* tht = ths + (size_t)t * BB * DLAT;
        float* yt  = ys  + (size_t)t * BB * DLAT;

        do_phase<0>(sm, blk, t == 0, Wg, bg, Wr, br,
                    noise + (size_t)t * BB * DLAT, hprev, ht, tht);
        grid_sync(tid);

        do_phase<1>(sm, blk, false, Wp, bp, Wo, bo, nullptr, ht, yt, nullptr);
        grid_sync(tid);

        do_out_prep(t, true, t + 1 < TS, false);
        grid_sync(tid);
    }
}

// ---------------------------------------------------------------------------
extern "C" void kernel_launch(void* const* d_in, const int* in_sizes, int n_in,
                              void* d_out, int out_size)
{
    (void)in_sizes; (void)n_in; (void)out_size;
    const float* obs   = (const float*)d_in[0];
    const float* smask = (const float*)d_in[1];
    const float* noise = (const float*)d_in[2];
    const float* W_pre = (const float*)d_in[3];
    const float* b_pre = (const float*)d_in[4];
    const float* Wg    = (const float*)d_in[5];
    const float* bg    = (const float*)d_in[6];
    const float* Wr    = (const float*)d_in[7];
    const float* br    = (const float*)d_in[8];
    const float* Wp    = (const float*)d_in[9];
    const float* bp    = (const float*)d_in[10];
    const float* Wo    = (const float*)d_in[11];
    const float* bo    = (const float*)d_in[12];
    const float* W_out = (const float*)d_in[13];
    const float* b_out = (const float*)d_in[14];

    float* out  = (float*)d_out;
    float* outs = out + OUTS_OFF;
    float* hs   = out + HS_OFF;
    float* ths  = out + TH_OFF;
    float* ys   = out + YS_OFF;
    float* dos_ = out + DO_OFF;

    mega_kernel<<<NB, 256>>>(obs, smask, noise,
                             W_pre, b_pre, Wg, bg, Wr, br, Wp, bp, Wo, bo,
                             W_out, b_out,
                             outs, hs, ths, ys, dos_);
}